// round 1
// baseline (speedup 1.0000x reference)
#include <cuda_runtime.h>
#include <math.h>
#include <stdint.h>

// ----------------------------------------------------------------------------
// ODELSTMCell: B=16384, I=128, H=256
//   ODE: 8 fixed RK45 (dopri5 tableau) steps of f(h)=tanh(h@W1^T+b1)@W2^T+b2
//   then two weight-shared LSTM cells.
// Strategy: persistent-tile CTA, MT=16 batch rows per CTA, all state kept in
// SMEM transposed [256][MT] (stride 20 to dodge bank conflicts). Weights
// pre-transposed to [K][J] in __device__ scratch so the GEMM inner loop does
// coalesced LDG of weight rows + SMEM broadcast of activations, accumulating
// with packed fma.rn.f32x2 (full-rate fp32 on sm_103a).
// ----------------------------------------------------------------------------

#define B_TOTAL 16384
#define HDIM    256
#define IDIM    128
#define MT      16     // batch rows per CTA  (16384 / 16 = 1024 CTAs exactly)
#define ST      20     // smem row stride in floats (pad 16 -> 20: 4-way max conflicts)
#define NSTEPS  8

// --- transposed weight scratch (module-static, allowed) ---
__device__ float g_W1t [HDIM * HDIM];        // [k][j]  W1t[k*256+j]  = W1[j*256+k]
__device__ float g_W2t [HDIM * HDIM];        // [k][j]
__device__ float g_Wiht[IDIM * 4 * HDIM];    // [k][j]  [128][1024]
__device__ float g_Whht[HDIM * 4 * HDIM];    // [k][j]  [256][1024]

__global__ void prep_kernel(const float* __restrict__ W1, const float* __restrict__ W2,
                            const float* __restrict__ Wih, const float* __restrict__ Whh) {
    int i0 = blockIdx.x * blockDim.x + threadIdx.x;
    int gs = gridDim.x * blockDim.x;
    for (int p = i0; p < HDIM * HDIM; p += gs) {          // p = j*256 + k
        int j = p >> 8, k = p & 255;
        g_W1t[k * HDIM + j] = W1[p];
        g_W2t[k * HDIM + j] = W2[p];
    }
    for (int p = i0; p < 4 * HDIM * IDIM; p += gs) {      // p = j*128 + k
        int j = p >> 7, k = p & 127;
        g_Wiht[k * (4 * HDIM) + j] = Wih[p];
    }
    for (int p = i0; p < 4 * HDIM * HDIM; p += gs) {      // p = j*256 + k
        int j = p >> 8, k = p & 255;
        g_Whht[k * (4 * HDIM) + j] = Whh[p];
    }
}

// --- packed fp32x2 FMA (sm_100+): d = a*b + d ---
__device__ __forceinline__ void ffma2(float2& d, float2 a, float2 b) {
    asm("fma.rn.f32x2 %0, %1, %2, %0;"
        : "+l"(*reinterpret_cast<unsigned long long*>(&d))
        : "l"(*reinterpret_cast<const unsigned long long*>(&a)),
          "l"(*reinterpret_cast<const unsigned long long*>(&b)));
}

__device__ __forceinline__ float4 LD4(const float* p) { return *reinterpret_cast<const float4*>(p); }
__device__ __forceinline__ void  ST4(float* p, float4 v) { *reinterpret_cast<float4*>(p) = v; }

__device__ __forceinline__ float sigm(float x) { return 1.0f / (1.0f + expf(-x)); }

// GEMM core: thread t owns output column j (Wcol = W + j), accumulates
// acc[p] over m-pairs (m = 2p, 2p+1) for the MT=16 rows.
//   acc[m] += sum_k inT[k][m] * W[k][j]
// inT: smem, [K][ST] transposed activations (reads are pure broadcast)
// W:   global, row-major [K][JST]
template<int K, int JST>
__device__ __forceinline__ void gemm_acc(const float* __restrict__ inT,
                                         const float* __restrict__ Wcol,
                                         float2 acc[8]) {
    const float* wp = Wcol;
    float w[8];
#pragma unroll
    for (int i = 0; i < 8; i++) w[i] = wp[i * JST];
#pragma unroll 1
    for (int k0 = 0; k0 < K; k0 += 8) {
        // prefetch next weight chunk (dummy re-read of chunk 0 on last iter)
        const float* wnp = (k0 + 8 < K) ? (wp + 8 * JST) : Wcol;
        float wn[8];
#pragma unroll
        for (int i = 0; i < 8; i++) wn[i] = wnp[i * JST];
#pragma unroll
        for (int i = 0; i < 8; i++) {
            const float* ap = inT + (k0 + i) * ST;
            float4 a0 = LD4(ap), a1 = LD4(ap + 4), a2 = LD4(ap + 8), a3 = LD4(ap + 12);
            float2 wv = make_float2(w[i], w[i]);
            ffma2(acc[0], make_float2(a0.x, a0.y), wv);
            ffma2(acc[1], make_float2(a0.z, a0.w), wv);
            ffma2(acc[2], make_float2(a1.x, a1.y), wv);
            ffma2(acc[3], make_float2(a1.z, a1.w), wv);
            ffma2(acc[4], make_float2(a2.x, a2.y), wv);
            ffma2(acc[5], make_float2(a2.z, a2.w), wv);
            ffma2(acc[6], make_float2(a3.x, a3.y), wv);
            ffma2(acc[7], make_float2(a3.z, a3.w), wv);
        }
#pragma unroll
        for (int i = 0; i < 8; i++) w[i] = wn[i];
        wp += 8 * JST;
    }
}

// one evaluation of f: out = tanh(in @ W1^T + b1) @ W2^T + b2
// ACCH: instead of writing out plainly, accumulate h += dt * (11/84) * f(in)
template<bool ACCH>
__device__ __forceinline__ void feval(const float* __restrict__ inT,
                                      float* __restrict__ outT,
                                      float* __restrict__ Tb,
                                      const float* __restrict__ dtm,
                                      int t, float b1j, float b2j) {
    float2 acc[8];
#pragma unroll
    for (int i = 0; i < 8; i++) acc[i] = make_float2(0.f, 0.f);
    gemm_acc<HDIM, HDIM>(inT, g_W1t + t, acc);
    {
        float* tw = Tb + t * ST;
#pragma unroll
        for (int p = 0; p < 8; p++) {
            tw[2 * p]     = tanhf(acc[p].x + b1j);
            tw[2 * p + 1] = tanhf(acc[p].y + b1j);
        }
    }
    __syncthreads();
#pragma unroll
    for (int i = 0; i < 8; i++) acc[i] = make_float2(0.f, 0.f);
    gemm_acc<HDIM, HDIM>(Tb, g_W2t + t, acc);
    float* ow = outT + t * ST;
    if (ACCH) {
        const float C6 = (float)(11.0 / 84.0);
#pragma unroll
        for (int p = 0; p < 8; p++) {
            ow[2 * p]     += dtm[2 * p]     * C6 * (acc[p].x + b2j);
            ow[2 * p + 1] += dtm[2 * p + 1] * C6 * (acc[p].y + b2j);
        }
    } else {
#pragma unroll
        for (int p = 0; p < 8; p++) {
            ow[2 * p]     = acc[p].x + b2j;
            ow[2 * p + 1] = acc[p].y + b2j;
        }
    }
    __syncthreads();
}

#define BUF (HDIM * ST)  // 5120 floats per state buffer
#define SMEM_FLOATS (8 * BUF + IDIM * ST + MT)
#define SMEM_BYTES  (SMEM_FLOATS * 4)

__global__ void __launch_bounds__(256, 1)
ode_lstm_kernel(const float* __restrict__ x,  const float* __restrict__ h0,
                const float* __restrict__ c0, const float* __restrict__ ts,
                const float* __restrict__ b_ih, const float* __restrict__ b_hh,
                const float* __restrict__ b1,   const float* __restrict__ b2,
                float* __restrict__ out) {
    extern __shared__ float s[];
    float* Hs = s;
    float* K1 = s + 1 * BUF;
    float* K2 = s + 2 * BUF;
    float* K3 = s + 3 * BUF;
    float* K4 = s + 4 * BUF;
    float* K5 = s + 5 * BUF;
    float* As = s + 6 * BUF;
    float* Tb = s + 7 * BUF;
    float* XT = s + 8 * BUF;          // [128][ST]
    float* DT = XT + IDIM * ST;       // [MT]

    const int t = threadIdx.x;
    const int rowBase = blockIdx.x * MT;

    // ---- loads (all coalesced across t) ----
#pragma unroll
    for (int m = 0; m < MT; m++)
        Hs[t * ST + m] = h0[(size_t)(rowBase + m) * HDIM + t];
    if (t < IDIM) {
#pragma unroll
        for (int m = 0; m < MT; m++)
            XT[t * ST + m] = x[(size_t)(rowBase + m) * IDIM + t];
    }
    if (t < MT) DT[t] = ts[rowBase + t] * (1.0f / NSTEPS);
    const float b1j = b1[t];
    const float b2j = b2[t];
    __syncthreads();

    float dtm[MT];
#pragma unroll
    for (int m = 0; m < MT; m++) dtm[m] = DT[m];

    // dopri5 tableau
    const float A21 = 0.2f;
    const float A31 = 0.075f, A32 = 0.225f;
    const float A41 = (float)(44.0 / 45.0), A42 = (float)(-56.0 / 15.0), A43 = (float)(32.0 / 9.0);
    const float A51 = (float)(19372.0 / 6561.0), A52 = (float)(-25360.0 / 2187.0),
                A53 = (float)(64448.0 / 6561.0), A54 = (float)(-212.0 / 729.0);
    const float A61 = (float)(9017.0 / 3168.0), A62 = (float)(-355.0 / 33.0),
                A63 = (float)(46732.0 / 5247.0), A64 = (float)(49.0 / 176.0),
                A65 = (float)(-5103.0 / 18656.0);
    const float C1 = (float)(35.0 / 384.0), C3 = (float)(500.0 / 1113.0),
                C4 = (float)(125.0 / 192.0), C5 = (float)(-2187.0 / 6784.0);

    const int b = t * ST;

    // ================= ODE: 8 RK45 steps =================
#pragma unroll 1
    for (int step = 0; step < NSTEPS; step++) {
        // k1 = f(h)
        feval<false>(Hs, K1, Tb, dtm, t, b1j, b2j);

        // A = h + dt*a21*k1
#pragma unroll
        for (int q = 0; q < 4; q++) {
            float h4[4], k1v[4], av[4];
            *(float4*)h4  = LD4(Hs + b + 4 * q);
            *(float4*)k1v = LD4(K1 + b + 4 * q);
#pragma unroll
            for (int c = 0; c < 4; c++)
                av[c] = h4[c] + dtm[4 * q + c] * (A21 * k1v[c]);
            ST4(As + b + 4 * q, *(float4*)av);
        }
        __syncthreads();
        feval<false>(As, K2, Tb, dtm, t, b1j, b2j);

        // A = h + dt*(a31 k1 + a32 k2)
#pragma unroll
        for (int q = 0; q < 4; q++) {
            float h4[4], k1v[4], k2v[4], av[4];
            *(float4*)h4  = LD4(Hs + b + 4 * q);
            *(float4*)k1v = LD4(K1 + b + 4 * q);
            *(float4*)k2v = LD4(K2 + b + 4 * q);
#pragma unroll
            for (int c = 0; c < 4; c++)
                av[c] = h4[c] + dtm[4 * q + c] * (A31 * k1v[c] + A32 * k2v[c]);
            ST4(As + b + 4 * q, *(float4*)av);
        }
        __syncthreads();
        feval<false>(As, K3, Tb, dtm, t, b1j, b2j);

        // A = h + dt*(a41 k1 + a42 k2 + a43 k3)
#pragma unroll
        for (int q = 0; q < 4; q++) {
            float h4[4], k1v[4], k2v[4], k3v[4], av[4];
            *(float4*)h4  = LD4(Hs + b + 4 * q);
            *(float4*)k1v = LD4(K1 + b + 4 * q);
            *(float4*)k2v = LD4(K2 + b + 4 * q);
            *(float4*)k3v = LD4(K3 + b + 4 * q);
#pragma unroll
            for (int c = 0; c < 4; c++)
                av[c] = h4[c] + dtm[4 * q + c] *
                        (A41 * k1v[c] + A42 * k2v[c] + A43 * k3v[c]);
            ST4(As + b + 4 * q, *(float4*)av);
        }
        __syncthreads();
        feval<false>(As, K4, Tb, dtm, t, b1j, b2j);

        // A = h + dt*(a51 k1 + a52 k2 + a53 k3 + a54 k4)
#pragma unroll
        for (int q = 0; q < 4; q++) {
            float h4[4], k1v[4], k2v[4], k3v[4], k4v[4], av[4];
            *(float4*)h4  = LD4(Hs + b + 4 * q);
            *(float4*)k1v = LD4(K1 + b + 4 * q);
            *(float4*)k2v = LD4(K2 + b + 4 * q);
            *(float4*)k3v = LD4(K3 + b + 4 * q);
            *(float4*)k4v = LD4(K4 + b + 4 * q);
#pragma unroll
            for (int c = 0; c < 4; c++)
                av[c] = h4[c] + dtm[4 * q + c] *
                        (A51 * k1v[c] + A52 * k2v[c] + A53 * k3v[c] + A54 * k4v[c]);
            ST4(As + b + 4 * q, *(float4*)av);
        }
        __syncthreads();
        feval<false>(As, K5, Tb, dtm, t, b1j, b2j);

        // A = h + dt*(a61..a65 · k);  h = h + dt*(c1 k1 + c3 k3 + c4 k4 + c5 k5)
#pragma unroll
        for (int q = 0; q < 4; q++) {
            float h4[4], k1v[4], k2v[4], k3v[4], k4v[4], k5v[4], av[4], hn[4];
            *(float4*)h4  = LD4(Hs + b + 4 * q);
            *(float4*)k1v = LD4(K1 + b + 4 * q);
            *(float4*)k2v = LD4(K2 + b + 4 * q);
            *(float4*)k3v = LD4(K3 + b + 4 * q);
            *(float4*)k4v = LD4(K4 + b + 4 * q);
            *(float4*)k5v = LD4(K5 + b + 4 * q);
#pragma unroll
            for (int c = 0; c < 4; c++) {
                float d = dtm[4 * q + c];
                av[c] = h4[c] + d * (A61 * k1v[c] + A62 * k2v[c] + A63 * k3v[c] +
                                     A64 * k4v[c] + A65 * k5v[c]);
                hn[c] = h4[c] + d * (C1 * k1v[c] + C3 * k3v[c] + C4 * k4v[c] + C5 * k5v[c]);
            }
            ST4(As + b + 4 * q, *(float4*)av);
            ST4(Hs + b + 4 * q, *(float4*)hn);
        }
        __syncthreads();
        // k6 = f(A); h += dt*(11/84)*k6  (fused epilogue)
        feval<true>(As, Hs, Tb, dtm, t, b1j, b2j);
    }

    // ================= two weight-shared LSTM cells =================
    float* Cs = K5;  // alias free buffers
    float* G0 = K1; float* G1 = K2; float* G2 = K3; float* G3 = K4;

#pragma unroll
    for (int m = 0; m < MT; m++)
        Cs[t * ST + m] = c0[(size_t)(rowBase + m) * HDIM + t];
    const float bz0 = b_ih[t]       + b_hh[t];
    const float bz1 = b_ih[256 + t] + b_hh[256 + t];
    const float bz2 = b_ih[512 + t] + b_hh[512 + t];
    const float bz3 = b_ih[768 + t] + b_hh[768 + t];
    __syncthreads();

#pragma unroll 1
    for (int cell = 0; cell < 2; cell++) {
#pragma unroll
        for (int q = 0; q < 4; q++) {
            float2 acc[8];
#pragma unroll
            for (int i = 0; i < 8; i++) acc[i] = make_float2(0.f, 0.f);
            gemm_acc<IDIM, 4 * HDIM>(XT, g_Wiht + q * HDIM + t, acc);
            gemm_acc<HDIM, 4 * HDIM>(Hs, g_Whht + q * HDIM + t, acc);
            float bq = (q == 0) ? bz0 : (q == 1) ? bz1 : (q == 2) ? bz2 : bz3;
            float* gw = ((q == 0) ? G0 : (q == 1) ? G1 : (q == 2) ? G2 : G3) + t * ST;
#pragma unroll
            for (int p = 0; p < 8; p++) {
                float vx = acc[p].x + bq, vy = acc[p].y + bq;
                if (q == 2) { gw[2 * p] = tanhf(vx); gw[2 * p + 1] = tanhf(vy); }
                else        { gw[2 * p] = sigm(vx);  gw[2 * p + 1] = sigm(vy);  }
            }
        }
        __syncthreads();
#pragma unroll
        for (int m = 0; m < MT; m++) {
            float iv = G0[b + m], fv = G1[b + m], gv = G2[b + m], ov = G3[b + m];
            float cn = fv * Cs[b + m] + iv * gv;
            Cs[b + m] = cn;
            Hs[b + m] = ov * tanhf(cn);
        }
        __syncthreads();
    }

    // ---- store h2 then c2 (coalesced) ----
    const size_t BH = (size_t)B_TOTAL * HDIM;
#pragma unroll
    for (int m = 0; m < MT; m++) {
        out[(size_t)(rowBase + m) * HDIM + t]      = Hs[t * ST + m];
        out[BH + (size_t)(rowBase + m) * HDIM + t] = Cs[t * ST + m];
    }
}

extern "C" void kernel_launch(void* const* d_in, const int* in_sizes, int n_in,
                              void* d_out, int out_size) {
    const float* x    = (const float*)d_in[0];
    const float* h0   = (const float*)d_in[1];
    const float* c0   = (const float*)d_in[2];
    const float* ts   = (const float*)d_in[3];
    const float* W_ih = (const float*)d_in[4];
    const float* W_hh = (const float*)d_in[5];
    const float* b_ih = (const float*)d_in[6];
    const float* b_hh = (const float*)d_in[7];
    const float* W1   = (const float*)d_in[8];
    const float* b1   = (const float*)d_in[9];
    const float* W2   = (const float*)d_in[10];
    const float* b2   = (const float*)d_in[11];
    float* out = (float*)d_out;

    cudaFuncSetAttribute(ode_lstm_kernel,
                         cudaFuncAttributeMaxDynamicSharedMemorySize, SMEM_BYTES);

    prep_kernel<<<512, 256>>>(W1, W2, W_ih, W_hh);
    ode_lstm_kernel<<<B_TOTAL / MT, 256, SMEM_BYTES>>>(
        x, h0, c0, ts, b_ih, b_hh, b1, b2, out);
}

// round 2
// speedup vs baseline: 1.0008x; 1.0008x over previous
#include <cuda_runtime.h>
#include <math.h>
#include <stdint.h>

// ----------------------------------------------------------------------------
// ODELSTMCell: B=16384, I=128, H=256
//   ODE: 8 fixed RK45 (dopri5 tableau) steps of f(h)=tanh(h@W1^T+b1)@W2^T+b2
//   then two weight-shared LSTM cells.
// Strategy: persistent-tile CTA, MT=16 batch rows per CTA, all state kept in
// SMEM transposed [256][MT] (stride 20 to dodge bank conflicts). Weights
// pre-transposed to [K][J] in __device__ scratch so the GEMM inner loop does
// coalesced LDG of weight rows + SMEM broadcast of activations, accumulating
// with packed fma.rn.f32x2 (full-rate fp32 on sm_103a).
// ----------------------------------------------------------------------------

#define B_TOTAL 16384
#define HDIM    256
#define IDIM    128
#define MT      16     // batch rows per CTA  (16384 / 16 = 1024 CTAs exactly)
#define ST      20     // smem row stride in floats (pad 16 -> 20: 4-way max conflicts)
#define NSTEPS  8

// --- transposed weight scratch (module-static, allowed) ---
__device__ float g_W1t [HDIM * HDIM];        // [k][j]  W1t[k*256+j]  = W1[j*256+k]
__device__ float g_W2t [HDIM * HDIM];        // [k][j]
__device__ float g_Wiht[IDIM * 4 * HDIM];    // [k][j]  [128][1024]
__device__ float g_Whht[HDIM * 4 * HDIM];    // [k][j]  [256][1024]

__global__ void prep_kernel(const float* __restrict__ W1, const float* __restrict__ W2,
                            const float* __restrict__ Wih, const float* __restrict__ Whh) {
    int i0 = blockIdx.x * blockDim.x + threadIdx.x;
    int gs = gridDim.x * blockDim.x;
    for (int p = i0; p < HDIM * HDIM; p += gs) {          // p = j*256 + k
        int j = p >> 8, k = p & 255;
        g_W1t[k * HDIM + j] = W1[p];
        g_W2t[k * HDIM + j] = W2[p];
    }
    for (int p = i0; p < 4 * HDIM * IDIM; p += gs) {      // p = j*128 + k
        int j = p >> 7, k = p & 127;
        g_Wiht[k * (4 * HDIM) + j] = Wih[p];
    }
    for (int p = i0; p < 4 * HDIM * HDIM; p += gs) {      // p = j*256 + k
        int j = p >> 8, k = p & 255;
        g_Whht[k * (4 * HDIM) + j] = Whh[p];
    }
}

// --- packed fp32x2 FMA (sm_100+): d = a*b + d ---
__device__ __forceinline__ void ffma2(float2& d, float2 a, float2 b) {
    asm("fma.rn.f32x2 %0, %1, %2, %0;"
        : "+l"(*reinterpret_cast<unsigned long long*>(&d))
        : "l"(*reinterpret_cast<const unsigned long long*>(&a)),
          "l"(*reinterpret_cast<const unsigned long long*>(&b)));
}

__device__ __forceinline__ float4 LD4(const float* p) { return *reinterpret_cast<const float4*>(p); }
__device__ __forceinline__ void  ST4(float* p, float4 v) { *reinterpret_cast<float4*>(p) = v; }

__device__ __forceinline__ float sigm(float x) { return 1.0f / (1.0f + expf(-x)); }

// GEMM core: thread t owns output column j (Wcol = W + j), accumulates
// acc[p] over m-pairs (m = 2p, 2p+1) for the MT=16 rows.
//   acc[m] += sum_k inT[k][m] * W[k][j]
// inT: smem, [K][ST] transposed activations (reads are pure broadcast)
// W:   global, row-major [K][JST]
template<int K, int JST>
__device__ __forceinline__ void gemm_acc(const float* __restrict__ inT,
                                         const float* __restrict__ Wcol,
                                         float2 acc[8]) {
    const float* wp = Wcol;
    float w[8];
#pragma unroll
    for (int i = 0; i < 8; i++) w[i] = wp[i * JST];
#pragma unroll 1
    for (int k0 = 0; k0 < K; k0 += 8) {
        // prefetch next weight chunk (dummy re-read of chunk 0 on last iter)
        const float* wnp = (k0 + 8 < K) ? (wp + 8 * JST) : Wcol;
        float wn[8];
#pragma unroll
        for (int i = 0; i < 8; i++) wn[i] = wnp[i * JST];
#pragma unroll
        for (int i = 0; i < 8; i++) {
            const float* ap = inT + (k0 + i) * ST;
            float4 a0 = LD4(ap), a1 = LD4(ap + 4), a2 = LD4(ap + 8), a3 = LD4(ap + 12);
            float2 wv = make_float2(w[i], w[i]);
            ffma2(acc[0], make_float2(a0.x, a0.y), wv);
            ffma2(acc[1], make_float2(a0.z, a0.w), wv);
            ffma2(acc[2], make_float2(a1.x, a1.y), wv);
            ffma2(acc[3], make_float2(a1.z, a1.w), wv);
            ffma2(acc[4], make_float2(a2.x, a2.y), wv);
            ffma2(acc[5], make_float2(a2.z, a2.w), wv);
            ffma2(acc[6], make_float2(a3.x, a3.y), wv);
            ffma2(acc[7], make_float2(a3.z, a3.w), wv);
        }
#pragma unroll
        for (int i = 0; i < 8; i++) w[i] = wn[i];
        wp += 8 * JST;
    }
}

// one evaluation of f: out = tanh(in @ W1^T + b1) @ W2^T + b2
// ACCH: instead of writing out plainly, accumulate h += dt * (11/84) * f(in)
template<bool ACCH>
__device__ __forceinline__ void feval(const float* __restrict__ inT,
                                      float* __restrict__ outT,
                                      float* __restrict__ Tb,
                                      const float* __restrict__ dtm,
                                      int t, float b1j, float b2j) {
    float2 acc[8];
#pragma unroll
    for (int i = 0; i < 8; i++) acc[i] = make_float2(0.f, 0.f);
    gemm_acc<HDIM, HDIM>(inT, g_W1t + t, acc);
    {
        float* tw = Tb + t * ST;
#pragma unroll
        for (int p = 0; p < 8; p++) {
            tw[2 * p]     = tanhf(acc[p].x + b1j);
            tw[2 * p + 1] = tanhf(acc[p].y + b1j);
        }
    }
    __syncthreads();
#pragma unroll
    for (int i = 0; i < 8; i++) acc[i] = make_float2(0.f, 0.f);
    gemm_acc<HDIM, HDIM>(Tb, g_W2t + t, acc);
    float* ow = outT + t * ST;
    if (ACCH) {
        const float C6 = (float)(11.0 / 84.0);
#pragma unroll
        for (int p = 0; p < 8; p++) {
            ow[2 * p]     += dtm[2 * p]     * C6 * (acc[p].x + b2j);
            ow[2 * p + 1] += dtm[2 * p + 1] * C6 * (acc[p].y + b2j);
        }
    } else {
#pragma unroll
        for (int p = 0; p < 8; p++) {
            ow[2 * p]     = acc[p].x + b2j;
            ow[2 * p + 1] = acc[p].y + b2j;
        }
    }
    __syncthreads();
}

#define BUF (HDIM * ST)  // 5120 floats per state buffer
#define SMEM_FLOATS (8 * BUF + IDIM * ST + MT)
#define SMEM_BYTES  (SMEM_FLOATS * 4)

__global__ void __launch_bounds__(256, 1)
ode_lstm_kernel(const float* __restrict__ x,  const float* __restrict__ h0,
                const float* __restrict__ c0, const float* __restrict__ ts,
                const float* __restrict__ b_ih, const float* __restrict__ b_hh,
                const float* __restrict__ b1,   const float* __restrict__ b2,
                float* __restrict__ out) {
    extern __shared__ float s[];
    float* Hs = s;
    float* K1 = s + 1 * BUF;
    float* K2 = s + 2 * BUF;
    float* K3 = s + 3 * BUF;
    float* K4 = s + 4 * BUF;
    float* K5 = s + 5 * BUF;
    float* As = s + 6 * BUF;
    float* Tb = s + 7 * BUF;
    float* XT = s + 8 * BUF;          // [128][ST]
    float* DT = XT + IDIM * ST;       // [MT]

    const int t = threadIdx.x;
    const int rowBase = blockIdx.x * MT;

    // ---- loads (all coalesced across t) ----
#pragma unroll
    for (int m = 0; m < MT; m++)
        Hs[t * ST + m] = h0[(size_t)(rowBase + m) * HDIM + t];
    if (t < IDIM) {
#pragma unroll
        for (int m = 0; m < MT; m++)
            XT[t * ST + m] = x[(size_t)(rowBase + m) * IDIM + t];
    }
    if (t < MT) DT[t] = ts[rowBase + t] * (1.0f / NSTEPS);
    const float b1j = b1[t];
    const float b2j = b2[t];
    __syncthreads();

    float dtm[MT];
#pragma unroll
    for (int m = 0; m < MT; m++) dtm[m] = DT[m];

    // dopri5 tableau
    const float A21 = 0.2f;
    const float A31 = 0.075f, A32 = 0.225f;
    const float A41 = (float)(44.0 / 45.0), A42 = (float)(-56.0 / 15.0), A43 = (float)(32.0 / 9.0);
    const float A51 = (float)(19372.0 / 6561.0), A52 = (float)(-25360.0 / 2187.0),
                A53 = (float)(64448.0 / 6561.0), A54 = (float)(-212.0 / 729.0);
    const float A61 = (float)(9017.0 / 3168.0), A62 = (float)(-355.0 / 33.0),
                A63 = (float)(46732.0 / 5247.0), A64 = (float)(49.0 / 176.0),
                A65 = (float)(-5103.0 / 18656.0);
    const float C1 = (float)(35.0 / 384.0), C3 = (float)(500.0 / 1113.0),
                C4 = (float)(125.0 / 192.0), C5 = (float)(-2187.0 / 6784.0);

    const int b = t * ST;

    // ================= ODE: 8 RK45 steps =================
#pragma unroll 1
    for (int step = 0; step < NSTEPS; step++) {
        // k1 = f(h)
        feval<false>(Hs, K1, Tb, dtm, t, b1j, b2j);

        // A = h + dt*a21*k1
#pragma unroll
        for (int q = 0; q < 4; q++) {
            float h4[4], k1v[4], av[4];
            *(float4*)h4  = LD4(Hs + b + 4 * q);
            *(float4*)k1v = LD4(K1 + b + 4 * q);
#pragma unroll
            for (int c = 0; c < 4; c++)
                av[c] = h4[c] + dtm[4 * q + c] * (A21 * k1v[c]);
            ST4(As + b + 4 * q, *(float4*)av);
        }
        __syncthreads();
        feval<false>(As, K2, Tb, dtm, t, b1j, b2j);

        // A = h + dt*(a31 k1 + a32 k2)
#pragma unroll
        for (int q = 0; q < 4; q++) {
            float h4[4], k1v[4], k2v[4], av[4];
            *(float4*)h4  = LD4(Hs + b + 4 * q);
            *(float4*)k1v = LD4(K1 + b + 4 * q);
            *(float4*)k2v = LD4(K2 + b + 4 * q);
#pragma unroll
            for (int c = 0; c < 4; c++)
                av[c] = h4[c] + dtm[4 * q + c] * (A31 * k1v[c] + A32 * k2v[c]);
            ST4(As + b + 4 * q, *(float4*)av);
        }
        __syncthreads();
        feval<false>(As, K3, Tb, dtm, t, b1j, b2j);

        // A = h + dt*(a41 k1 + a42 k2 + a43 k3)
#pragma unroll
        for (int q = 0; q < 4; q++) {
            float h4[4], k1v[4], k2v[4], k3v[4], av[4];
            *(float4*)h4  = LD4(Hs + b + 4 * q);
            *(float4*)k1v = LD4(K1 + b + 4 * q);
            *(float4*)k2v = LD4(K2 + b + 4 * q);
            *(float4*)k3v = LD4(K3 + b + 4 * q);
#pragma unroll
            for (int c = 0; c < 4; c++)
                av[c] = h4[c] + dtm[4 * q + c] *
                        (A41 * k1v[c] + A42 * k2v[c] + A43 * k3v[c]);
            ST4(As + b + 4 * q, *(float4*)av);
        }
        __syncthreads();
        feval<false>(As, K4, Tb, dtm, t, b1j, b2j);

        // A = h + dt*(a51 k1 + a52 k2 + a53 k3 + a54 k4)
#pragma unroll
        for (int q = 0; q < 4; q++) {
            float h4[4], k1v[4], k2v[4], k3v[4], k4v[4], av[4];
            *(float4*)h4  = LD4(Hs + b + 4 * q);
            *(float4*)k1v = LD4(K1 + b + 4 * q);
            *(float4*)k2v = LD4(K2 + b + 4 * q);
            *(float4*)k3v = LD4(K3 + b + 4 * q);
            *(float4*)k4v = LD4(K4 + b + 4 * q);
#pragma unroll
            for (int c = 0; c < 4; c++)
                av[c] = h4[c] + dtm[4 * q + c] *
                        (A51 * k1v[c] + A52 * k2v[c] + A53 * k3v[c] + A54 * k4v[c]);
            ST4(As + b + 4 * q, *(float4*)av);
        }
        __syncthreads();
        feval<false>(As, K5, Tb, dtm, t, b1j, b2j);

        // A = h + dt*(a61..a65 · k);  h = h + dt*(c1 k1 + c3 k3 + c4 k4 + c5 k5)
#pragma unroll
        for (int q = 0; q < 4; q++) {
            float h4[4], k1v[4], k2v[4], k3v[4], k4v[4], k5v[4], av[4], hn[4];
            *(float4*)h4  = LD4(Hs + b + 4 * q);
            *(float4*)k1v = LD4(K1 + b + 4 * q);
            *(float4*)k2v = LD4(K2 + b + 4 * q);
            *(float4*)k3v = LD4(K3 + b + 4 * q);
            *(float4*)k4v = LD4(K4 + b + 4 * q);
            *(float4*)k5v = LD4(K5 + b + 4 * q);
#pragma unroll
            for (int c = 0; c < 4; c++) {
                float d = dtm[4 * q + c];
                av[c] = h4[c] + d * (A61 * k1v[c] + A62 * k2v[c] + A63 * k3v[c] +
                                     A64 * k4v[c] + A65 * k5v[c]);
                hn[c] = h4[c] + d * (C1 * k1v[c] + C3 * k3v[c] + C4 * k4v[c] + C5 * k5v[c]);
            }
            ST4(As + b + 4 * q, *(float4*)av);
            ST4(Hs + b + 4 * q, *(float4*)hn);
        }
        __syncthreads();
        // k6 = f(A); h += dt*(11/84)*k6  (fused epilogue)
        feval<true>(As, Hs, Tb, dtm, t, b1j, b2j);
    }

    // ================= two weight-shared LSTM cells =================
    float* Cs = K5;  // alias free buffers
    float* G0 = K1; float* G1 = K2; float* G2 = K3; float* G3 = K4;

#pragma unroll
    for (int m = 0; m < MT; m++)
        Cs[t * ST + m] = c0[(size_t)(rowBase + m) * HDIM + t];
    const float bz0 = b_ih[t]       + b_hh[t];
    const float bz1 = b_ih[256 + t] + b_hh[256 + t];
    const float bz2 = b_ih[512 + t] + b_hh[512 + t];
    const float bz3 = b_ih[768 + t] + b_hh[768 + t];
    __syncthreads();

#pragma unroll 1
    for (int cell = 0; cell < 2; cell++) {
#pragma unroll
        for (int q = 0; q < 4; q++) {
            float2 acc[8];
#pragma unroll
            for (int i = 0; i < 8; i++) acc[i] = make_float2(0.f, 0.f);
            gemm_acc<IDIM, 4 * HDIM>(XT, g_Wiht + q * HDIM + t, acc);
            gemm_acc<HDIM, 4 * HDIM>(Hs, g_Whht + q * HDIM + t, acc);
            float bq = (q == 0) ? bz0 : (q == 1) ? bz1 : (q == 2) ? bz2 : bz3;
            float* gw = ((q == 0) ? G0 : (q == 1) ? G1 : (q == 2) ? G2 : G3) + t * ST;
#pragma unroll
            for (int p = 0; p < 8; p++) {
                float vx = acc[p].x + bq, vy = acc[p].y + bq;
                if (q == 2) { gw[2 * p] = tanhf(vx); gw[2 * p + 1] = tanhf(vy); }
                else        { gw[2 * p] = sigm(vx);  gw[2 * p + 1] = sigm(vy);  }
            }
        }
        __syncthreads();
#pragma unroll
        for (int m = 0; m < MT; m++) {
            float iv = G0[b + m], fv = G1[b + m], gv = G2[b + m], ov = G3[b + m];
            float cn = fv * Cs[b + m] + iv * gv;
            Cs[b + m] = cn;
            Hs[b + m] = ov * tanhf(cn);
        }
        __syncthreads();
    }

    // ---- store h2 then c2 (coalesced) ----
    const size_t BH = (size_t)B_TOTAL * HDIM;
#pragma unroll
    for (int m = 0; m < MT; m++) {
        out[(size_t)(rowBase + m) * HDIM + t]      = Hs[t * ST + m];
        out[BH + (size_t)(rowBase + m) * HDIM + t] = Cs[t * ST + m];
    }
}

extern "C" void kernel_launch(void* const* d_in, const int* in_sizes, int n_in,
                              void* d_out, int out_size) {
    const float* x    = (const float*)d_in[0];
    const float* h0   = (const float*)d_in[1];
    const float* c0   = (const float*)d_in[2];
    const float* ts   = (const float*)d_in[3];
    const float* W_ih = (const float*)d_in[4];
    const float* W_hh = (const float*)d_in[5];
    const float* b_ih = (const float*)d_in[6];
    const float* b_hh = (const float*)d_in[7];
    const float* W1   = (const float*)d_in[8];
    const float* b1   = (const float*)d_in[9];
    const float* W2   = (const float*)d_in[10];
    const float* b2   = (const float*)d_in[11];
    float* out = (float*)d_out;

    cudaFuncSetAttribute(ode_lstm_kernel,
                         cudaFuncAttributeMaxDynamicSharedMemorySize, SMEM_BYTES);

    prep_kernel<<<512, 256>>>(W1, W2, W_ih, W_hh);
    ode_lstm_kernel<<<B_TOTAL / MT, 256, SMEM_BYTES>>>(
        x, h0, c0, ts, b_ih, b_hh, b1, b2, out);
}

// round 3
// speedup vs baseline: 1.0011x; 1.0003x over previous
#include <cuda_runtime.h>
#include <math.h>
#include <stdint.h>

// ----------------------------------------------------------------------------
// ODELSTMCell: B=16384, I=128, H=256
//   ODE: 8 fixed RK45 (dopri5 tableau) steps of f(h)=tanh(h@W1^T+b1)@W2^T+b2
//   then two weight-shared LSTM cells.
// Strategy: persistent-tile CTA, MT=16 batch rows per CTA, all state kept in
// SMEM transposed [256][MT] (stride 20 to dodge bank conflicts). Weights
// pre-transposed to [K][J] in __device__ scratch so the GEMM inner loop does
// coalesced LDG of weight rows + SMEM broadcast of activations, accumulating
// with packed fma.rn.f32x2 (full-rate fp32 on sm_103a).
// ----------------------------------------------------------------------------

#define B_TOTAL 16384
#define HDIM    256
#define IDIM    128
#define MT      16     // batch rows per CTA  (16384 / 16 = 1024 CTAs exactly)
#define ST      20     // smem row stride in floats (pad 16 -> 20: 4-way max conflicts)
#define NSTEPS  8

// --- transposed weight scratch (module-static, allowed) ---
__device__ float g_W1t [HDIM * HDIM];        // [k][j]  W1t[k*256+j]  = W1[j*256+k]
__device__ float g_W2t [HDIM * HDIM];        // [k][j]
__device__ float g_Wiht[IDIM * 4 * HDIM];    // [k][j]  [128][1024]
__device__ float g_Whht[HDIM * 4 * HDIM];    // [k][j]  [256][1024]

__global__ void prep_kernel(const float* __restrict__ W1, const float* __restrict__ W2,
                            const float* __restrict__ Wih, const float* __restrict__ Whh) {
    int i0 = blockIdx.x * blockDim.x + threadIdx.x;
    int gs = gridDim.x * blockDim.x;
    for (int p = i0; p < HDIM * HDIM; p += gs) {          // p = j*256 + k
        int j = p >> 8, k = p & 255;
        g_W1t[k * HDIM + j] = W1[p];
        g_W2t[k * HDIM + j] = W2[p];
    }
    for (int p = i0; p < 4 * HDIM * IDIM; p += gs) {      // p = j*128 + k
        int j = p >> 7, k = p & 127;
        g_Wiht[k * (4 * HDIM) + j] = Wih[p];
    }
    for (int p = i0; p < 4 * HDIM * HDIM; p += gs) {      // p = j*256 + k
        int j = p >> 8, k = p & 255;
        g_Whht[k * (4 * HDIM) + j] = Whh[p];
    }
}

// --- packed fp32x2 FMA (sm_100+): d = a*b + d ---
__device__ __forceinline__ void ffma2(float2& d, float2 a, float2 b) {
    asm("fma.rn.f32x2 %0, %1, %2, %0;"
        : "+l"(*reinterpret_cast<unsigned long long*>(&d))
        : "l"(*reinterpret_cast<const unsigned long long*>(&a)),
          "l"(*reinterpret_cast<const unsigned long long*>(&b)));
}

__device__ __forceinline__ float4 LD4(const float* p) { return *reinterpret_cast<const float4*>(p); }
__device__ __forceinline__ void  ST4(float* p, float4 v) { *reinterpret_cast<float4*>(p) = v; }

__device__ __forceinline__ float sigm(float x) { return 1.0f / (1.0f + expf(-x)); }

// GEMM core: thread t owns output column j (Wcol = W + j), accumulates
// acc[p] over m-pairs (m = 2p, 2p+1) for the MT=16 rows.
//   acc[m] += sum_k inT[k][m] * W[k][j]
// inT: smem, [K][ST] transposed activations (reads are pure broadcast)
// W:   global, row-major [K][JST]
template<int K, int JST>
__device__ __forceinline__ void gemm_acc(const float* __restrict__ inT,
                                         const float* __restrict__ Wcol,
                                         float2 acc[8]) {
    const float* wp = Wcol;
    float w[8];
#pragma unroll
    for (int i = 0; i < 8; i++) w[i] = wp[i * JST];
#pragma unroll 1
    for (int k0 = 0; k0 < K; k0 += 8) {
        // prefetch next weight chunk (dummy re-read of chunk 0 on last iter)
        const float* wnp = (k0 + 8 < K) ? (wp + 8 * JST) : Wcol;
        float wn[8];
#pragma unroll
        for (int i = 0; i < 8; i++) wn[i] = wnp[i * JST];
#pragma unroll
        for (int i = 0; i < 8; i++) {
            const float* ap = inT + (k0 + i) * ST;
            float4 a0 = LD4(ap), a1 = LD4(ap + 4), a2 = LD4(ap + 8), a3 = LD4(ap + 12);
            float2 wv = make_float2(w[i], w[i]);
            ffma2(acc[0], make_float2(a0.x, a0.y), wv);
            ffma2(acc[1], make_float2(a0.z, a0.w), wv);
            ffma2(acc[2], make_float2(a1.x, a1.y), wv);
            ffma2(acc[3], make_float2(a1.z, a1.w), wv);
            ffma2(acc[4], make_float2(a2.x, a2.y), wv);
            ffma2(acc[5], make_float2(a2.z, a2.w), wv);
            ffma2(acc[6], make_float2(a3.x, a3.y), wv);
            ffma2(acc[7], make_float2(a3.z, a3.w), wv);
        }
#pragma unroll
        for (int i = 0; i < 8; i++) w[i] = wn[i];
        wp += 8 * JST;
    }
}

// one evaluation of f: out = tanh(in @ W1^T + b1) @ W2^T + b2
// ACCH: instead of writing out plainly, accumulate h += dt * (11/84) * f(in)
template<bool ACCH>
__device__ __forceinline__ void feval(const float* __restrict__ inT,
                                      float* __restrict__ outT,
                                      float* __restrict__ Tb,
                                      const float* __restrict__ dtm,
                                      int t, float b1j, float b2j) {
    float2 acc[8];
#pragma unroll
    for (int i = 0; i < 8; i++) acc[i] = make_float2(0.f, 0.f);
    gemm_acc<HDIM, HDIM>(inT, g_W1t + t, acc);
    {
        float* tw = Tb + t * ST;
#pragma unroll
        for (int p = 0; p < 8; p++) {
            tw[2 * p]     = tanhf(acc[p].x + b1j);
            tw[2 * p + 1] = tanhf(acc[p].y + b1j);
        }
    }
    __syncthreads();
#pragma unroll
    for (int i = 0; i < 8; i++) acc[i] = make_float2(0.f, 0.f);
    gemm_acc<HDIM, HDIM>(Tb, g_W2t + t, acc);
    float* ow = outT + t * ST;
    if (ACCH) {
        const float C6 = (float)(11.0 / 84.0);
#pragma unroll
        for (int p = 0; p < 8; p++) {
            ow[2 * p]     += dtm[2 * p]     * C6 * (acc[p].x + b2j);
            ow[2 * p + 1] += dtm[2 * p + 1] * C6 * (acc[p].y + b2j);
        }
    } else {
#pragma unroll
        for (int p = 0; p < 8; p++) {
            ow[2 * p]     = acc[p].x + b2j;
            ow[2 * p + 1] = acc[p].y + b2j;
        }
    }
    __syncthreads();
}

#define BUF (HDIM * ST)  // 5120 floats per state buffer
#define SMEM_FLOATS (8 * BUF + IDIM * ST + MT)
#define SMEM_BYTES  (SMEM_FLOATS * 4)

__global__ void __launch_bounds__(256, 1)
ode_lstm_kernel(const float* __restrict__ x,  const float* __restrict__ h0,
                const float* __restrict__ c0, const float* __restrict__ ts,
                const float* __restrict__ b_ih, const float* __restrict__ b_hh,
                const float* __restrict__ b1,   const float* __restrict__ b2,
                float* __restrict__ out) {
    extern __shared__ float s[];
    float* Hs = s;
    float* K1 = s + 1 * BUF;
    float* K2 = s + 2 * BUF;
    float* K3 = s + 3 * BUF;
    float* K4 = s + 4 * BUF;
    float* K5 = s + 5 * BUF;
    float* As = s + 6 * BUF;
    float* Tb = s + 7 * BUF;
    float* XT = s + 8 * BUF;          // [128][ST]
    float* DT = XT + IDIM * ST;       // [MT]

    const int t = threadIdx.x;
    const int rowBase = blockIdx.x * MT;

    // ---- loads (all coalesced across t) ----
#pragma unroll
    for (int m = 0; m < MT; m++)
        Hs[t * ST + m] = h0[(size_t)(rowBase + m) * HDIM + t];
    if (t < IDIM) {
#pragma unroll
        for (int m = 0; m < MT; m++)
            XT[t * ST + m] = x[(size_t)(rowBase + m) * IDIM + t];
    }
    if (t < MT) DT[t] = ts[rowBase + t] * (1.0f / NSTEPS);
    const float b1j = b1[t];
    const float b2j = b2[t];
    __syncthreads();

    float dtm[MT];
#pragma unroll
    for (int m = 0; m < MT; m++) dtm[m] = DT[m];

    // dopri5 tableau
    const float A21 = 0.2f;
    const float A31 = 0.075f, A32 = 0.225f;
    const float A41 = (float)(44.0 / 45.0), A42 = (float)(-56.0 / 15.0), A43 = (float)(32.0 / 9.0);
    const float A51 = (float)(19372.0 / 6561.0), A52 = (float)(-25360.0 / 2187.0),
                A53 = (float)(64448.0 / 6561.0), A54 = (float)(-212.0 / 729.0);
    const float A61 = (float)(9017.0 / 3168.0), A62 = (float)(-355.0 / 33.0),
                A63 = (float)(46732.0 / 5247.0), A64 = (float)(49.0 / 176.0),
                A65 = (float)(-5103.0 / 18656.0);
    const float C1 = (float)(35.0 / 384.0), C3 = (float)(500.0 / 1113.0),
                C4 = (float)(125.0 / 192.0), C5 = (float)(-2187.0 / 6784.0);

    const int b = t * ST;

    // ================= ODE: 8 RK45 steps =================
#pragma unroll 1
    for (int step = 0; step < NSTEPS; step++) {
        // k1 = f(h)
        feval<false>(Hs, K1, Tb, dtm, t, b1j, b2j);

        // A = h + dt*a21*k1
#pragma unroll
        for (int q = 0; q < 4; q++) {
            float h4[4], k1v[4], av[4];
            *(float4*)h4  = LD4(Hs + b + 4 * q);
            *(float4*)k1v = LD4(K1 + b + 4 * q);
#pragma unroll
            for (int c = 0; c < 4; c++)
                av[c] = h4[c] + dtm[4 * q + c] * (A21 * k1v[c]);
            ST4(As + b + 4 * q, *(float4*)av);
        }
        __syncthreads();
        feval<false>(As, K2, Tb, dtm, t, b1j, b2j);

        // A = h + dt*(a31 k1 + a32 k2)
#pragma unroll
        for (int q = 0; q < 4; q++) {
            float h4[4], k1v[4], k2v[4], av[4];
            *(float4*)h4  = LD4(Hs + b + 4 * q);
            *(float4*)k1v = LD4(K1 + b + 4 * q);
            *(float4*)k2v = LD4(K2 + b + 4 * q);
#pragma unroll
            for (int c = 0; c < 4; c++)
                av[c] = h4[c] + dtm[4 * q + c] * (A31 * k1v[c] + A32 * k2v[c]);
            ST4(As + b + 4 * q, *(float4*)av);
        }
        __syncthreads();
        feval<false>(As, K3, Tb, dtm, t, b1j, b2j);

        // A = h + dt*(a41 k1 + a42 k2 + a43 k3)
#pragma unroll
        for (int q = 0; q < 4; q++) {
            float h4[4], k1v[4], k2v[4], k3v[4], av[4];
            *(float4*)h4  = LD4(Hs + b + 4 * q);
            *(float4*)k1v = LD4(K1 + b + 4 * q);
            *(float4*)k2v = LD4(K2 + b + 4 * q);
            *(float4*)k3v = LD4(K3 + b + 4 * q);
#pragma unroll
            for (int c = 0; c < 4; c++)
                av[c] = h4[c] + dtm[4 * q + c] *
                        (A41 * k1v[c] + A42 * k2v[c] + A43 * k3v[c]);
            ST4(As + b + 4 * q, *(float4*)av);
        }
        __syncthreads();
        feval<false>(As, K4, Tb, dtm, t, b1j, b2j);

        // A = h + dt*(a51 k1 + a52 k2 + a53 k3 + a54 k4)
#pragma unroll
        for (int q = 0; q < 4; q++) {
            float h4[4], k1v[4], k2v[4], k3v[4], k4v[4], av[4];
            *(float4*)h4  = LD4(Hs + b + 4 * q);
            *(float4*)k1v = LD4(K1 + b + 4 * q);
            *(float4*)k2v = LD4(K2 + b + 4 * q);
            *(float4*)k3v = LD4(K3 + b + 4 * q);
            *(float4*)k4v = LD4(K4 + b + 4 * q);
#pragma unroll
            for (int c = 0; c < 4; c++)
                av[c] = h4[c] + dtm[4 * q + c] *
                        (A51 * k1v[c] + A52 * k2v[c] + A53 * k3v[c] + A54 * k4v[c]);
            ST4(As + b + 4 * q, *(float4*)av);
        }
        __syncthreads();
        feval<false>(As, K5, Tb, dtm, t, b1j, b2j);

        // A = h + dt*(a61..a65 · k);  h = h + dt*(c1 k1 + c3 k3 + c4 k4 + c5 k5)
#pragma unroll
        for (int q = 0; q < 4; q++) {
            float h4[4], k1v[4], k2v[4], k3v[4], k4v[4], k5v[4], av[4], hn[4];
            *(float4*)h4  = LD4(Hs + b + 4 * q);
            *(float4*)k1v = LD4(K1 + b + 4 * q);
            *(float4*)k2v = LD4(K2 + b + 4 * q);
            *(float4*)k3v = LD4(K3 + b + 4 * q);
            *(float4*)k4v = LD4(K4 + b + 4 * q);
            *(float4*)k5v = LD4(K5 + b + 4 * q);
#pragma unroll
            for (int c = 0; c < 4; c++) {
                float d = dtm[4 * q + c];
                av[c] = h4[c] + d * (A61 * k1v[c] + A62 * k2v[c] + A63 * k3v[c] +
                                     A64 * k4v[c] + A65 * k5v[c]);
                hn[c] = h4[c] + d * (C1 * k1v[c] + C3 * k3v[c] + C4 * k4v[c] + C5 * k5v[c]);
            }
            ST4(As + b + 4 * q, *(float4*)av);
            ST4(Hs + b + 4 * q, *(float4*)hn);
        }
        __syncthreads();
        // k6 = f(A); h += dt*(11/84)*k6  (fused epilogue)
        feval<true>(As, Hs, Tb, dtm, t, b1j, b2j);
    }

    // ================= two weight-shared LSTM cells =================
    float* Cs = K5;  // alias free buffers
    float* G0 = K1; float* G1 = K2; float* G2 = K3; float* G3 = K4;

#pragma unroll
    for (int m = 0; m < MT; m++)
        Cs[t * ST + m] = c0[(size_t)(rowBase + m) * HDIM + t];
    const float bz0 = b_ih[t]       + b_hh[t];
    const float bz1 = b_ih[256 + t] + b_hh[256 + t];
    const float bz2 = b_ih[512 + t] + b_hh[512 + t];
    const float bz3 = b_ih[768 + t] + b_hh[768 + t];
    __syncthreads();

#pragma unroll 1
    for (int cell = 0; cell < 2; cell++) {
#pragma unroll
        for (int q = 0; q < 4; q++) {
            float2 acc[8];
#pragma unroll
            for (int i = 0; i < 8; i++) acc[i] = make_float2(0.f, 0.f);
            gemm_acc<IDIM, 4 * HDIM>(XT, g_Wiht + q * HDIM + t, acc);
            gemm_acc<HDIM, 4 * HDIM>(Hs, g_Whht + q * HDIM + t, acc);
            float bq = (q == 0) ? bz0 : (q == 1) ? bz1 : (q == 2) ? bz2 : bz3;
            float* gw = ((q == 0) ? G0 : (q == 1) ? G1 : (q == 2) ? G2 : G3) + t * ST;
#pragma unroll
            for (int p = 0; p < 8; p++) {
                float vx = acc[p].x + bq, vy = acc[p].y + bq;
                if (q == 2) { gw[2 * p] = tanhf(vx); gw[2 * p + 1] = tanhf(vy); }
                else        { gw[2 * p] = sigm(vx);  gw[2 * p + 1] = sigm(vy);  }
            }
        }
        __syncthreads();
#pragma unroll
        for (int m = 0; m < MT; m++) {
            float iv = G0[b + m], fv = G1[b + m], gv = G2[b + m], ov = G3[b + m];
            float cn = fv * Cs[b + m] + iv * gv;
            Cs[b + m] = cn;
            Hs[b + m] = ov * tanhf(cn);
        }
        __syncthreads();
    }

    // ---- store h2 then c2 (coalesced) ----
    const size_t BH = (size_t)B_TOTAL * HDIM;
#pragma unroll
    for (int m = 0; m < MT; m++) {
        out[(size_t)(rowBase + m) * HDIM + t]      = Hs[t * ST + m];
        out[BH + (size_t)(rowBase + m) * HDIM + t] = Cs[t * ST + m];
    }
}

extern "C" void kernel_launch(void* const* d_in, const int* in_sizes, int n_in,
                              void* d_out, int out_size) {
    const float* x    = (const float*)d_in[0];
    const float* h0   = (const float*)d_in[1];
    const float* c0   = (const float*)d_in[2];
    const float* ts   = (const float*)d_in[3];
    const float* W_ih = (const float*)d_in[4];
    const float* W_hh = (const float*)d_in[5];
    const float* b_ih = (const float*)d_in[6];
    const float* b_hh = (const float*)d_in[7];
    const float* W1   = (const float*)d_in[8];
    const float* b1   = (const float*)d_in[9];
    const float* W2   = (const float*)d_in[10];
    const float* b2   = (const float*)d_in[11];
    float* out = (float*)d_out;

    cudaFuncSetAttribute(ode_lstm_kernel,
                         cudaFuncAttributeMaxDynamicSharedMemorySize, SMEM_BYTES);

    prep_kernel<<<512, 256>>>(W1, W2, W_ih, W_hh);
    ode_lstm_kernel<<<B_TOTAL / MT, 256, SMEM_BYTES>>>(
        x, h0, c0, ts, b_ih, b_hh, b1, b2, out);
}